// round 8
// baseline (speedup 1.0000x reference)
#include <cuda_runtime.h>
#include <math.h>

#define J 20
#define F4PJ 17   // float4s per joint (odd stride -> conflict-free broadcast)
#define TS  388   // t-slot stride in floats (== 4 mod 32)
#define WSTRIDE 1952
// per joint: f4[0..8]=(M0,M1,M2,p_rev), f4[9..11]=(Rpri row, v_pri), f4[12]=p_pri, f4[13..15]=(Rtrk row, p_trk)

__device__ __forceinline__ void rpy2r_fast(float r, float p, float y, float* R) {
    float cr, sr, cp, sp, cy, sy;
    __sincosf(r, &sr, &cr);
    __sincosf(p, &sp, &cp);
    __sincosf(y, &sy, &cy);
    R[0] = cy * cp; R[1] = cy * sp * sr - sy * cr; R[2] = cy * sp * cr + sy * sr;
    R[3] = sy * cp; R[4] = sy * sp * sr + cy * cr; R[5] = sy * sp * cr - cy * sr;
    R[6] = -sp;     R[7] = cp * sr;                R[8] = cp * cr;
}

__device__ __forceinline__ void mm3(float* D, const float* A, const float* B) {
#pragma unroll
    for (int r = 0; r < 3; r++)
#pragma unroll
        for (int c = 0; c < 3; c++)
            D[r * 3 + c] = fmaf(A[r * 3 + 0], B[0 * 3 + c],
                           fmaf(A[r * 3 + 1], B[1 * 3 + c],
                                A[r * 3 + 2] * B[2 * 3 + c]));
}

__device__ __forceinline__ void joint_apply_v(const float4* __restrict__ C,
                                              float s, float ic, float qp,
                                              float R[9], float p[3],
                                              float R1[9], float p1[3]) {
    float Rs[9], prev[3];
#pragma unroll
    for (int i = 0; i < 9; i++) {
        float4 f = C[i];
        Rs[i] = fmaf(s, f.y, fmaf(ic, f.z, f.x));
        if (i < 3) prev[i] = f.w;
    }
    mm3(R1, R, Rs);
#pragma unroll
    for (int r = 0; r < 3; r++)
        p1[r] = fmaf(R[r*3+0], prev[0], fmaf(R[r*3+1], prev[1], fmaf(R[r*3+2], prev[2], p[r])));
    float4 b0 = C[9], b1 = C[10], b2 = C[11], pq = C[12];
    float ps0 = fmaf(qp, b0.w, pq.x);
    float ps1 = fmaf(qp, b1.w, pq.y);
    float ps2 = fmaf(qp, b2.w, pq.z);
    float R2[9];
#pragma unroll
    for (int r = 0; r < 3; r++) {
        R2[r*3+0] = fmaf(R1[r*3+0], b0.x, fmaf(R1[r*3+1], b1.x, R1[r*3+2] * b2.x));
        R2[r*3+1] = fmaf(R1[r*3+0], b0.y, fmaf(R1[r*3+1], b1.y, R1[r*3+2] * b2.y));
        R2[r*3+2] = fmaf(R1[r*3+0], b0.z, fmaf(R1[r*3+1], b1.z, R1[r*3+2] * b2.z));
    }
#pragma unroll
    for (int r = 0; r < 3; r++)
        p[r] = fmaf(R1[r*3+0], ps0, fmaf(R1[r*3+1], ps1, fmaf(R1[r*3+2], ps2, p1[r])));
#pragma unroll
    for (int i = 0; i < 9; i++) R[i] = R2[i];
}

__device__ __forceinline__ void stage12(float* dst, const float R[9], const float p[3]) {
    float4* sp = (float4*)dst;
    sp[0] = make_float4(R[0], R[1], R[2], p[0]);
    sp[1] = make_float4(R[3], R[4], R[5], p[1]);
    sp[2] = make_float4(R[6], R[7], R[8], p[2]);
}

__global__ void __launch_bounds__(128, 6)
fk_kernel(const float* __restrict__ rev_q, const float* __restrict__ pri_q,
          const float* __restrict__ rev_p_off, const float* __restrict__ rev_rpy_off,
          const float* __restrict__ pri_p_off, const float* __restrict__ pri_rpy_off,
          const float* __restrict__ rev_axis, const float* __restrict__ pri_axis,
          const float* __restrict__ p_track, const float* __restrict__ rpy_track,
          float* __restrict__ out, int B) {
    __shared__ float4 sC4[J * F4PJ];
    __shared__ float sStage[4 * WSTRIDE];

    int tid  = threadIdx.x;
    int lane = tid & 31;
    int w    = tid >> 5;
    int bb   = lane >> 2;      // batch within warp (0..7)
    int s    = lane & 3;       // segment id
    int wb0  = blockIdx.x * 32 + w * 8;
    int gb   = wb0 + bb; if (gb >= B) gb = B - 1;

    int len = 6 - 2 * (s & 1);        // 6,4,6,4
    int jb  = 5 * s + (s & 1);        // segment base joint: 0,6,10,16

    // q loads + trig early
    float sn[6], ic[6], qp[6];
#pragma unroll
    for (int i = 0; i < 6; i++) {
        sn[i] = 0.f; ic[i] = 0.f; qp[i] = 0.f;
        if (i < len) {
            float q = rev_q[(size_t)gb * J + jb + i];
            float c;
            __sincosf(q, &sn[i], &c);
            ic[i] = 1.f - c;
            qp[i] = pri_q[(size_t)gb * J + jb + i];
        }
    }

    // ---- in-block constant prep (threads 0..19) ----
    if (tid < J) {
        int j = tid;
        float4* C = sC4 + j * F4PJ;
        float Ro[9];
        rpy2r_fast(rev_rpy_off[j*3+0], rev_rpy_off[j*3+1], rev_rpy_off[j*3+2], Ro);
        float ax = rev_axis[j*3+0], ay = rev_axis[j*3+1], az = rev_axis[j*3+2];
        float n = sqrtf(ax*ax + ay*ay + az*az) + 1e-12f;
        ax /= n; ay /= n; az /= n;
        float K[9]  = {0.f, -az, ay,  az, 0.f, -ax,  -ay, ax, 0.f};
        float K2[9]; mm3(K2, K, K);
        float M1[9], M2[9]; mm3(M1, Ro, K); mm3(M2, Ro, K2);
        float pr[3] = {rev_p_off[j*3+0], rev_p_off[j*3+1], rev_p_off[j*3+2]};
#pragma unroll
        for (int i = 0; i < 9; i++)
            C[i] = make_float4(Ro[i], M1[i], M2[i], i < 3 ? pr[i] : 0.f);

        float Rp[9];
        rpy2r_fast(pri_rpy_off[j*3+0], pri_rpy_off[j*3+1], pri_rpy_off[j*3+2], Rp);
        float pax = pri_axis[j*3+0], pay = pri_axis[j*3+1], paz = pri_axis[j*3+2];
#pragma unroll
        for (int r = 0; r < 3; r++) {
            float v = Rp[r*3+0]*pax + Rp[r*3+1]*pay + Rp[r*3+2]*paz;
            C[9 + r] = make_float4(Rp[r*3+0], Rp[r*3+1], Rp[r*3+2], v);
        }
        C[12] = make_float4(pri_p_off[j*3+0], pri_p_off[j*3+1], pri_p_off[j*3+2], 0.f);

        float Rt[9];
        rpy2r_fast(rpy_track[j*3+0], rpy_track[j*3+1], rpy_track[j*3+2], Rt);
#pragma unroll
        for (int r = 0; r < 3; r++)
            C[13 + r] = make_float4(Rt[r*3+0], Rt[r*3+1], Rt[r*3+2], p_track[j*3+r]);
    }
    __syncthreads();

    // ---- phase 1: local segment product ----
    float R[9] = {1.f,0.f,0.f, 0.f,1.f,0.f, 0.f,0.f,1.f};
    float p[3] = {0.f, 0.f, 0.f};
#pragma unroll
    for (int i = 0; i < 6; i++) {
        if (i < len) {
            const float4* C = sC4 + (jb + i) * F4PJ;
            float R1[9], p1[3];
            joint_apply_v(C, sn[i], ic[i], qp[i], R, p, R1, p1);
        }
    }

    // ---- phase 2: exclusive prefix within 4-lane group via shfl ----
    float P[9] = {1.f,0.f,0.f, 0.f,1.f,0.f, 0.f,0.f,1.f};
    float pp[3] = {0.f, 0.f, 0.f};
    int base = lane & ~3;
#pragma unroll
    for (int k = 0; k < 3; k++) {
        float Lr[9], Lp[3];
#pragma unroll
        for (int t = 0; t < 9; t++) Lr[t] = __shfl_sync(0xffffffffu, R[t], base + k);
#pragma unroll
        for (int t = 0; t < 3; t++) Lp[t] = __shfl_sync(0xffffffffu, p[t], base + k);
        if (k < s) {
            float pn[3];
#pragma unroll
            for (int r = 0; r < 3; r++)
                pn[r] = fmaf(P[r*3+0], Lp[0],
                        fmaf(P[r*3+1], Lp[1],
                        fmaf(P[r*3+2], Lp[2], pp[r])));
            float Rn[9];
            mm3(Rn, P, Lr);
#pragma unroll
            for (int t = 0; t < 9; t++) P[t] = Rn[t];
            pp[0] = pn[0]; pp[1] = pn[1]; pp[2] = pn[2];
        }
    }

    // ---- phase 3: re-run from prefix, staged pair-drains ----
    float* wbase = sStage + w * WSTRIDE;
    float* stgR = wbase;           // 2 x TS
    float* stgP = wbase + 2 * TS;  // 2 x TS
    float* stgT = wbase + 4 * TS;  // 1 x TS

    float* outTrk = out;
    float* outRev = out + (size_t)B * 160;
    float* outPri = out + (size_t)B * 480;

#pragma unroll
    for (int t = 0; t < 9; t++) R[t] = P[t];
    p[0] = pp[0]; p[1] = pp[1]; p[2] = pp[2];

    bool fast = (wb0 + 8 <= B);
    const float4 hom = make_float4(0.f, 0.f, 0.f, 1.f);

    if (fast) {
#pragma unroll
        for (int i = 0; i < 6; i++) {
            if (i < len) {
                const float4* C = sC4 + (jb + i) * F4PJ;
                float R1[9], p1[3];
                joint_apply_v(C, sn[i], ic[i], qp[i], R, p, R1, p1);
                int t = i & 1;
                stage12(stgR + t * TS + lane * 12, R1, p1);
                stage12(stgP + t * TS + lane * 12, R, p);
                if ((i & 1) == 0) {   // tracking joint (jb even => j parity == i parity)
                    float4 t0 = C[13], t1 = C[14], t2 = C[15];
                    float Rt[9], pt[3];
#pragma unroll
                    for (int r = 0; r < 3; r++) {
                        Rt[r*3+0] = fmaf(R[r*3+0], t0.x, fmaf(R[r*3+1], t1.x, R[r*3+2] * t2.x));
                        Rt[r*3+1] = fmaf(R[r*3+0], t0.y, fmaf(R[r*3+1], t1.y, R[r*3+2] * t2.y));
                        Rt[r*3+2] = fmaf(R[r*3+0], t0.z, fmaf(R[r*3+1], t1.z, R[r*3+2] * t2.z));
                        pt[r] = fmaf(R[r*3+0], t0.w, fmaf(R[r*3+1], t1.w, fmaf(R[r*3+2], t2.w, p[r])));
                    }
                    stage12(stgT + lane * 12, Rt, pt);
                }
            }
            __syncwarp();

            if (i & 1) {
                // ---- rev/pri pair drains: slots (jb' + i-1, jb' + i), 128B-aligned lines ----
                if (i < 5) {
                    // full: all 4 segments, 8 insts each array
#pragma unroll
                    for (int k = 0; k < 8; k++) {
                        int c = k * 32 + lane;
                        int row = c & 3, st = (c >> 2) & 1, rec = c >> 3;
                        int bbd = rec >> 2, sd = rec & 3;
                        int slot = 5 * sd + (sd & 1) + (i - 1) + st;
                        size_t d = ((size_t)(wb0 + bbd) * J + slot) * 16 + 4 * row;
                        float4 vr = (row < 3) ? *(const float4*)(stgR + st * TS + rec * 12 + 4 * row) : hom;
                        float4 vp = (row < 3) ? *(const float4*)(stgP + st * TS + rec * 12 + 4 * row) : hom;
                        *(float4*)(outRev + d) = vr;
                        *(float4*)(outPri + d) = vp;
                    }
                } else {
                    // half: even segments only (len==6), 4 insts each array
#pragma unroll
                    for (int k = 0; k < 4; k++) {
                        int c = k * 32 + lane;
                        int row = c & 3, st = (c >> 2) & 1, rec = c >> 3;  // 0..15
                        int bbd = rec >> 1, sd = (rec & 1) * 2;
                        int src = bbd * 4 + sd;
                        int slot = 5 * sd + 4 + st;
                        size_t d = ((size_t)(wb0 + bbd) * J + slot) * 16 + 4 * row;
                        float4 vr = (row < 3) ? *(const float4*)(stgR + st * TS + src * 12 + 4 * row) : hom;
                        float4 vp = (row < 3) ? *(const float4*)(stgP + st * TS + src * 12 + 4 * row) : hom;
                        *(float4*)(outRev + d) = vr;
                        *(float4*)(outPri + d) = vp;
                    }
                }
            } else {
                // ---- track drains ----
                int it = i >> 1;
                if (i < 4) {
                    // full: all 4 segments own a frame
#pragma unroll
                    for (int k = 0; k < 4; k++) {
                        int c = k * 32 + lane;
                        int row = c & 3, rec = c >> 2;   // 0..31
                        int bbd = rec >> 2, sd = rec & 3;
                        int tb = (5 * sd + (sd & 1)) >> 1;   // 0,3,5,8
                        float4 v = (row < 3) ? *(const float4*)(stgT + rec * 12 + 4 * row) : hom;
                        *(float4*)(outTrk + ((size_t)(wb0 + bbd) * 10 + tb + it) * 16 + 4 * row) = v;
                    }
                } else {
                    // half: even segments only
#pragma unroll
                    for (int k = 0; k < 2; k++) {
                        int c = k * 32 + lane;
                        int row = c & 3, rec = c >> 2;   // 0..15
                        int bbd = rec >> 1, sd = (rec & 1) * 2;
                        int src = bbd * 4 + sd;
                        int tb = (5 * sd) >> 1;          // 0,5
                        float4 v = (row < 3) ? *(const float4*)(stgT + src * 12 + 4 * row) : hom;
                        *(float4*)(outTrk + ((size_t)(wb0 + bbd) * 10 + tb + it) * 16 + 4 * row) = v;
                    }
                }
            }
            __syncwarp();
        }
    } else {
        // generic tail path: per-lane direct stores (correctness only)
#pragma unroll
        for (int i = 0; i < 6; i++) {
            if (i < len) {
                const float4* C = sC4 + (jb + i) * F4PJ;
                float R1[9], p1[3];
                joint_apply_v(C, sn[i], ic[i], qp[i], R, p, R1, p1);
                int j = jb + i;
                float* dR = outRev + ((size_t)gb * J + j) * 16;
                float* dP = outPri + ((size_t)gb * J + j) * 16;
                *(float4*)(dR + 0)  = make_float4(R1[0], R1[1], R1[2], p1[0]);
                *(float4*)(dR + 4)  = make_float4(R1[3], R1[4], R1[5], p1[1]);
                *(float4*)(dR + 8)  = make_float4(R1[6], R1[7], R1[8], p1[2]);
                *(float4*)(dR + 12) = hom;
                *(float4*)(dP + 0)  = make_float4(R[0], R[1], R[2], p[0]);
                *(float4*)(dP + 4)  = make_float4(R[3], R[4], R[5], p[1]);
                *(float4*)(dP + 8)  = make_float4(R[6], R[7], R[8], p[2]);
                *(float4*)(dP + 12) = hom;
                if ((i & 1) == 0) {
                    float4 t0 = C[13], t1 = C[14], t2 = C[15];
                    float Rt[9], pt[3];
#pragma unroll
                    for (int r = 0; r < 3; r++) {
                        Rt[r*3+0] = fmaf(R[r*3+0], t0.x, fmaf(R[r*3+1], t1.x, R[r*3+2] * t2.x));
                        Rt[r*3+1] = fmaf(R[r*3+0], t0.y, fmaf(R[r*3+1], t1.y, R[r*3+2] * t2.y));
                        Rt[r*3+2] = fmaf(R[r*3+0], t0.z, fmaf(R[r*3+1], t1.z, R[r*3+2] * t2.z));
                        pt[r] = fmaf(R[r*3+0], t0.w, fmaf(R[r*3+1], t1.w, fmaf(R[r*3+2], t2.w, p[r])));
                    }
                    float* dT = outTrk + ((size_t)gb * 10 + (j >> 1)) * 16;
                    *(float4*)(dT + 0)  = make_float4(Rt[0], Rt[1], Rt[2], pt[0]);
                    *(float4*)(dT + 4)  = make_float4(Rt[3], Rt[4], Rt[5], pt[1]);
                    *(float4*)(dT + 8)  = make_float4(Rt[6], Rt[7], Rt[8], pt[2]);
                    *(float4*)(dT + 12) = hom;
                }
            }
        }
    }
}

extern "C" void kernel_launch(void* const* d_in, const int* in_sizes, int n_in,
                              void* d_out, int out_size) {
    const float* rev_q       = (const float*)d_in[0];
    const float* pri_q       = (const float*)d_in[1];
    const float* rev_p_off   = (const float*)d_in[2];
    const float* rev_rpy_off = (const float*)d_in[3];
    const float* pri_p_off   = (const float*)d_in[4];
    const float* pri_rpy_off = (const float*)d_in[5];
    const float* rev_axis    = (const float*)d_in[6];
    const float* pri_axis    = (const float*)d_in[7];
    const float* p_track     = (const float*)d_in[8];
    const float* rpy_track   = (const float*)d_in[9];
    float* out = (float*)d_out;

    int B = in_sizes[0] / J;
    int grid = (B + 31) / 32;
    fk_kernel<<<grid, 128>>>(rev_q, pri_q,
                             rev_p_off, rev_rpy_off, pri_p_off, pri_rpy_off,
                             rev_axis, pri_axis, p_track, rpy_track, out, B);
}

// round 9
// speedup vs baseline: 1.2989x; 1.2989x over previous
#include <cuda_runtime.h>
#include <math.h>

#define J 20
#define JPS 5
#define F4PJ 17   // float4s per joint (ODD stride -> conflict-free broadcast LDS.128)
// f4[0..8]  : (M0[i], M1[i], M2[i], i<3 ? p_rev[i] : 0)
// f4[9..11] : (Rpri row r, v_pri[r])
// f4[12]    : (p_pri[0..2], 0)
// f4[13..15]: (Rtrk row r, p_trk[r])
// f4[16]    : pad

__device__ __forceinline__ void rpy2r_fast(float r, float p, float y, float* R) {
    float cr, sr, cp, sp, cy, sy;
    __sincosf(r, &sr, &cr);
    __sincosf(p, &sp, &cp);
    __sincosf(y, &sy, &cy);
    R[0] = cy * cp; R[1] = cy * sp * sr - sy * cr; R[2] = cy * sp * cr + sy * sr;
    R[3] = sy * cp; R[4] = sy * sp * sr + cy * cr; R[5] = sy * sp * cr - cy * sr;
    R[6] = -sp;     R[7] = cp * sr;                R[8] = cp * cr;
}

__device__ __forceinline__ void mm3(float* D, const float* A, const float* B) {
#pragma unroll
    for (int r = 0; r < 3; r++)
#pragma unroll
        for (int c = 0; c < 3; c++)
            D[r * 3 + c] = fmaf(A[r * 3 + 0], B[0 * 3 + c],
                           fmaf(A[r * 3 + 1], B[1 * 3 + c],
                                A[r * 3 + 2] * B[2 * 3 + c]));
}

// joint apply with vectorized constants (13 LDS.128 per call)
__device__ __forceinline__ void joint_apply_v(const float4* __restrict__ C,
                                              float s, float ic, float qp,
                                              float R[9], float p[3],
                                              float R1[9], float p1[3]) {
    float Rs[9], prev[3];
#pragma unroll
    for (int i = 0; i < 9; i++) {
        float4 f = C[i];
        Rs[i] = fmaf(s, f.y, fmaf(ic, f.z, f.x));
        if (i < 3) prev[i] = f.w;
    }
    mm3(R1, R, Rs);
#pragma unroll
    for (int r = 0; r < 3; r++)
        p1[r] = fmaf(R[r*3+0], prev[0], fmaf(R[r*3+1], prev[1], fmaf(R[r*3+2], prev[2], p[r])));
    float4 b0 = C[9], b1 = C[10], b2 = C[11], pq = C[12];
    float ps0 = fmaf(qp, b0.w, pq.x);
    float ps1 = fmaf(qp, b1.w, pq.y);
    float ps2 = fmaf(qp, b2.w, pq.z);
    float R2[9];
#pragma unroll
    for (int r = 0; r < 3; r++) {
        R2[r*3+0] = fmaf(R1[r*3+0], b0.x, fmaf(R1[r*3+1], b1.x, R1[r*3+2] * b2.x));
        R2[r*3+1] = fmaf(R1[r*3+0], b0.y, fmaf(R1[r*3+1], b1.y, R1[r*3+2] * b2.y));
        R2[r*3+2] = fmaf(R1[r*3+0], b0.z, fmaf(R1[r*3+1], b1.z, R1[r*3+2] * b2.z));
    }
#pragma unroll
    for (int r = 0; r < 3; r++)
        p[r] = fmaf(R1[r*3+0], ps0, fmaf(R1[r*3+1], ps1, fmaf(R1[r*3+2], ps2, p1[r])));
#pragma unroll
    for (int i = 0; i < 9; i++) R[i] = R2[i];
}

// R4's proven emits: 12-float stride staging, clamped (single code path).
__device__ __forceinline__ void emit_full(float* stg, int lane, int i, int wb0, int B,
                                          float* __restrict__ tbase,
                                          const float R[9], const float p[3]) {
    float4* sp = (float4*)(stg + lane * 12);
    sp[0] = make_float4(R[0], R[1], R[2], p[0]);
    sp[1] = make_float4(R[3], R[4], R[5], p[1]);
    sp[2] = make_float4(R[6], R[7], R[8], p[2]);
    __syncwarp();
#pragma unroll
    for (int k = 0; k < 4; k++) {
        int c = k * 32 + lane, idx = c >> 2, m = c & 3;
        int bb = idx >> 2, s2 = idx & 3;
        int gb = wb0 + bb; if (gb >= B) gb = B - 1;
        float4 v = (m < 3) ? *(const float4*)(stg + idx * 12 + 4 * m)
                           : make_float4(0.f, 0.f, 0.f, 1.f);
        *(float4*)(tbase + ((size_t)gb * J + 5 * s2 + i) * 16 + 4 * m) = v;
    }
    __syncwarp();
}

__device__ __forceinline__ void emit_track(float* stg, int lane, int i, int wb0, int B,
                                           float* __restrict__ tbase,
                                           const float R[9], const float p[3], bool owner) {
    if (owner) {
        float4* sp = (float4*)(stg + lane * 12);
        sp[0] = make_float4(R[0], R[1], R[2], p[0]);
        sp[1] = make_float4(R[3], R[4], R[5], p[1]);
        sp[2] = make_float4(R[6], R[7], R[8], p[2]);
    }
    __syncwarp();
#pragma unroll
    for (int k = 0; k < 2; k++) {
        int c = k * 32 + lane, idx16 = c >> 2, m = c & 3;
        int bb = idx16 >> 1, pos = idx16 & 1;
        int s2 = (i & 1) + 2 * pos;
        int src = bb * 4 + s2;
        int slot = (5 * s2 + i) >> 1;
        int gb = wb0 + bb; if (gb >= B) gb = B - 1;
        float4 v = (m < 3) ? *(const float4*)(stg + src * 12 + 4 * m)
                           : make_float4(0.f, 0.f, 0.f, 1.f);
        *(float4*)(tbase + ((size_t)gb * (J / 2) + slot) * 16 + 4 * m) = v;
    }
    __syncwarp();
}

__global__ void __launch_bounds__(128, 7)
fk_kernel(const float* __restrict__ rev_q, const float* __restrict__ pri_q,
          const float* __restrict__ rev_p_off, const float* __restrict__ rev_rpy_off,
          const float* __restrict__ pri_p_off, const float* __restrict__ pri_rpy_off,
          const float* __restrict__ rev_axis, const float* __restrict__ pri_axis,
          const float* __restrict__ p_track, const float* __restrict__ rpy_track,
          float* __restrict__ out, int B) {
    __shared__ float4 sC4[J * F4PJ];
    __shared__ float sStage[4][32 * 12];

    int tid  = threadIdx.x;
    int lane = tid & 31;
    int w    = tid >> 5;
    int bb   = lane >> 2;
    int s    = lane & 3;
    int wb0  = blockIdx.x * 32 + w * 8;
    int gb   = wb0 + bb; if (gb >= B) gb = B - 1;

    // q loads + trig early (overlap with const prep)
    float sn[JPS], ic[JPS], qp[JPS];
#pragma unroll
    for (int i = 0; i < JPS; i++) {
        float q = rev_q[(size_t)gb * J + s * JPS + i];
        float c;
        __sincosf(q, &sn[i], &c);
        ic[i] = 1.f - c;
        qp[i] = pri_q[(size_t)gb * J + s * JPS + i];
    }

    // ---- in-block constant prep (threads 0..19) ----
    if (tid < J) {
        int j = tid;
        float4* C = sC4 + j * F4PJ;
        float Ro[9];
        rpy2r_fast(rev_rpy_off[j*3+0], rev_rpy_off[j*3+1], rev_rpy_off[j*3+2], Ro);
        float ax = rev_axis[j*3+0], ay = rev_axis[j*3+1], az = rev_axis[j*3+2];
        float n = sqrtf(ax*ax + ay*ay + az*az) + 1e-12f;
        ax /= n; ay /= n; az /= n;
        float K[9]  = {0.f, -az, ay,  az, 0.f, -ax,  -ay, ax, 0.f};
        float K2[9]; mm3(K2, K, K);
        float M1[9], M2[9]; mm3(M1, Ro, K); mm3(M2, Ro, K2);
        float pr[3] = {rev_p_off[j*3+0], rev_p_off[j*3+1], rev_p_off[j*3+2]};
#pragma unroll
        for (int i = 0; i < 9; i++)
            C[i] = make_float4(Ro[i], M1[i], M2[i], i < 3 ? pr[i] : 0.f);

        float Rp[9];
        rpy2r_fast(pri_rpy_off[j*3+0], pri_rpy_off[j*3+1], pri_rpy_off[j*3+2], Rp);
        float pax = pri_axis[j*3+0], pay = pri_axis[j*3+1], paz = pri_axis[j*3+2];
#pragma unroll
        for (int r = 0; r < 3; r++) {
            float v = Rp[r*3+0]*pax + Rp[r*3+1]*pay + Rp[r*3+2]*paz;
            C[9 + r] = make_float4(Rp[r*3+0], Rp[r*3+1], Rp[r*3+2], v);
        }
        C[12] = make_float4(pri_p_off[j*3+0], pri_p_off[j*3+1], pri_p_off[j*3+2], 0.f);

        float Rt[9];
        rpy2r_fast(rpy_track[j*3+0], rpy_track[j*3+1], rpy_track[j*3+2], Rt);
#pragma unroll
        for (int r = 0; r < 3; r++)
            C[13 + r] = make_float4(Rt[r*3+0], Rt[r*3+1], Rt[r*3+2], p_track[j*3+r]);
    }
    __syncthreads();

    // ---- phase 1: local segment product ----
    float R[9] = {1.f,0.f,0.f, 0.f,1.f,0.f, 0.f,0.f,1.f};
    float p[3] = {0.f, 0.f, 0.f};
#pragma unroll
    for (int i = 0; i < JPS; i++) {
        const float4* C = sC4 + (s * JPS + i) * F4PJ;
        float R1[9], p1[3];
        joint_apply_v(C, sn[i], ic[i], qp[i], R, p, R1, p1);
    }

    // ---- phase 2: exclusive prefix within 4-lane group via shfl ----
    float P[9] = {1.f,0.f,0.f, 0.f,1.f,0.f, 0.f,0.f,1.f};
    float pp[3] = {0.f, 0.f, 0.f};
    int base = lane & ~3;
#pragma unroll
    for (int k = 0; k < 3; k++) {
        float Lr[9], Lp[3];
#pragma unroll
        for (int t = 0; t < 9; t++) Lr[t] = __shfl_sync(0xffffffffu, R[t], base + k);
#pragma unroll
        for (int t = 0; t < 3; t++) Lp[t] = __shfl_sync(0xffffffffu, p[t], base + k);
        if (k < s) {
            float pn[3];
#pragma unroll
            for (int r = 0; r < 3; r++)
                pn[r] = fmaf(P[r*3+0], Lp[0],
                        fmaf(P[r*3+1], Lp[1],
                        fmaf(P[r*3+2], Lp[2], pp[r])));
            float Rn[9];
            mm3(Rn, P, Lr);
#pragma unroll
            for (int t = 0; t < 9; t++) P[t] = Rn[t];
            pp[0] = pn[0]; pp[1] = pn[1]; pp[2] = pn[2];
        }
    }

    // ---- phase 3: re-run from prefix, emitting (R4 emit path) ----
    float* stg = sStage[w];
    float* outTrk = out;
    float* outRev = out + (size_t)B * 160;
    float* outPri = out + (size_t)B * 480;

#pragma unroll
    for (int t = 0; t < 9; t++) R[t] = P[t];
    p[0] = pp[0]; p[1] = pp[1]; p[2] = pp[2];

#pragma unroll
    for (int i = 0; i < JPS; i++) {
        int j = s * JPS + i;
        const float4* C = sC4 + j * F4PJ;
        float R1[9], p1[3];
        joint_apply_v(C, sn[i], ic[i], qp[i], R, p, R1, p1);
        emit_full(stg, lane, i, wb0, B, outRev, R1, p1);
        emit_full(stg, lane, i, wb0, B, outPri, R, p);

        bool owner = (((s ^ i) & 1) == 0);   // j = 5s+i even <=> s,i same parity
        float Rt[9] = {0}, pt[3] = {0};
        if (owner) {
            float4 t0 = C[13], t1 = C[14], t2 = C[15];
#pragma unroll
            for (int r = 0; r < 3; r++) {
                Rt[r*3+0] = fmaf(R[r*3+0], t0.x, fmaf(R[r*3+1], t1.x, R[r*3+2] * t2.x));
                Rt[r*3+1] = fmaf(R[r*3+0], t0.y, fmaf(R[r*3+1], t1.y, R[r*3+2] * t2.y));
                Rt[r*3+2] = fmaf(R[r*3+0], t0.z, fmaf(R[r*3+1], t1.z, R[r*3+2] * t2.z));
                pt[r] = fmaf(R[r*3+0], t0.w, fmaf(R[r*3+1], t1.w, fmaf(R[r*3+2], t2.w, p[r])));
            }
        }
        emit_track(stg, lane, i, wb0, B, outTrk, Rt, pt, owner);
    }
}

extern "C" void kernel_launch(void* const* d_in, const int* in_sizes, int n_in,
                              void* d_out, int out_size) {
    const float* rev_q       = (const float*)d_in[0];
    const float* pri_q       = (const float*)d_in[1];
    const float* rev_p_off   = (const float*)d_in[2];
    const float* rev_rpy_off = (const float*)d_in[3];
    const float* pri_p_off   = (const float*)d_in[4];
    const float* pri_rpy_off = (const float*)d_in[5];
    const float* rev_axis    = (const float*)d_in[6];
    const float* pri_axis    = (const float*)d_in[7];
    const float* p_track     = (const float*)d_in[8];
    const float* rpy_track   = (const float*)d_in[9];
    float* out = (float*)d_out;

    int B = in_sizes[0] / J;
    int grid = (B + 31) / 32;
    fk_kernel<<<grid, 128>>>(rev_q, pri_q,
                             rev_p_off, rev_rpy_off, pri_p_off, pri_rpy_off,
                             rev_axis, pri_axis, p_track, rpy_track, out, B);
}

// round 10
// speedup vs baseline: 1.3149x; 1.0123x over previous
#include <cuda_runtime.h>
#include <math.h>

#define J 20
#define CONST_PER_J 57
#define REGSZ 384          // floats per staging region (32 lanes * 12)
#define WSTRIDE (4 * REGSZ)
// per joint: M0[9]@0, M1[9]@9, M2[9]@18, p_rev[3]@27,
//            Rpri[9]@30, v_pri[3]@39, p_pri[3]@42, Rtrk[9]@45, p_trk[3]@54

__device__ __forceinline__ void rpy2r_fast(float r, float p, float y, float* R) {
    float cr, sr, cp, sp, cy, sy;
    __sincosf(r, &sr, &cr);
    __sincosf(p, &sp, &cp);
    __sincosf(y, &sy, &cy);
    R[0] = cy * cp; R[1] = cy * sp * sr - sy * cr; R[2] = cy * sp * cr + sy * sr;
    R[3] = sy * cp; R[4] = sy * sp * sr + cy * cr; R[5] = sy * sp * cr - cy * sr;
    R[6] = -sp;     R[7] = cp * sr;                R[8] = cp * cr;
}

__device__ __forceinline__ void mm3(float* D, const float* A, const float* B) {
#pragma unroll
    for (int r = 0; r < 3; r++)
#pragma unroll
        for (int c = 0; c < 3; c++)
            D[r * 3 + c] = fmaf(A[r * 3 + 0], B[0 * 3 + c],
                           fmaf(A[r * 3 + 1], B[1 * 3 + c],
                                A[r * 3 + 2] * B[2 * 3 + c]));
}

// R4's scalar-constant joint apply (proven fastest constant path)
__device__ __forceinline__ void joint_apply_c(const float* C, float s, float ic, float qp,
                                              float R[9], float p[3],
                                              float R1[9], float p1[3]) {
    float Rs[9];
#pragma unroll
    for (int i = 0; i < 9; i++)
        Rs[i] = fmaf(s, C[9 + i], fmaf(ic, C[18 + i], C[i]));
    mm3(R1, R, Rs);
#pragma unroll
    for (int r = 0; r < 3; r++)
        p1[r] = fmaf(R[r * 3 + 0], C[27],
                fmaf(R[r * 3 + 1], C[28],
                fmaf(R[r * 3 + 2], C[29], p[r])));
    float ps0 = fmaf(qp, C[39], C[42]);
    float ps1 = fmaf(qp, C[40], C[43]);
    float ps2 = fmaf(qp, C[41], C[44]);
    float R2[9];
    mm3(R2, R1, C + 30);
#pragma unroll
    for (int r = 0; r < 3; r++)
        p[r] = fmaf(R1[r * 3 + 0], ps0,
               fmaf(R1[r * 3 + 1], ps1,
               fmaf(R1[r * 3 + 2], ps2, p1[r])));
#pragma unroll
    for (int i = 0; i < 9; i++) R[i] = R2[i];
}

__device__ __forceinline__ void stage12(float* dst, const float R[9], const float p[3]) {
    float4* sp = (float4*)dst;
    sp[0] = make_float4(R[0], R[1], R[2], p[0]);
    sp[1] = make_float4(R[3], R[4], R[5], p[1]);
    sp[2] = make_float4(R[6], R[7], R[8], p[2]);
}

__global__ void __launch_bounds__(128, 7)
fk_kernel(const float* __restrict__ rev_q, const float* __restrict__ pri_q,
          const float* __restrict__ rev_p_off, const float* __restrict__ rev_rpy_off,
          const float* __restrict__ pri_p_off, const float* __restrict__ pri_rpy_off,
          const float* __restrict__ rev_axis, const float* __restrict__ pri_axis,
          const float* __restrict__ p_track, const float* __restrict__ rpy_track,
          float* __restrict__ out, int B) {
    __shared__ float sC[J * CONST_PER_J];
    __shared__ float sStage[4 * WSTRIDE];  // per warp: R0,R1,P0,P1 (track reuses R1)

    int tid  = threadIdx.x;
    int lane = tid & 31;
    int w    = tid >> 5;
    int bb   = lane >> 2;              // batch within warp (0..7)
    int s    = lane & 3;               // segment id
    int wb0  = blockIdx.x * 32 + w * 8;
    int gb   = wb0 + bb; if (gb >= B) gb = B - 1;

    int len = 6 - 2 * (s & 1);         // 6,4,6,4
    int jb  = 5 * s + (s & 1);         // 0,6,10,16 (even bases)

    // q loads + trig early (overlap with const prep)
    float sn[6], ic[6], qp[6];
#pragma unroll
    for (int i = 0; i < 6; i++) {
        sn[i] = 0.f; ic[i] = 0.f; qp[i] = 0.f;
        if (i < len) {
            float q = rev_q[(size_t)gb * J + jb + i];
            float c;
            __sincosf(q, &sn[i], &c);
            ic[i] = 1.f - c;
            qp[i] = pri_q[(size_t)gb * J + jb + i];
        }
    }

    // ---- in-block constant prep (threads 0..19), R4-identical ----
    if (tid < J) {
        int j = tid;
        float* C = sC + j * CONST_PER_J;
        float Ro[9];
        rpy2r_fast(rev_rpy_off[j*3+0], rev_rpy_off[j*3+1], rev_rpy_off[j*3+2], Ro);
        float ax = rev_axis[j*3+0], ay = rev_axis[j*3+1], az = rev_axis[j*3+2];
        float n = sqrtf(ax*ax + ay*ay + az*az) + 1e-12f;
        ax /= n; ay /= n; az /= n;
        float K[9]  = {0.f, -az, ay,  az, 0.f, -ax,  -ay, ax, 0.f};
        float K2[9]; mm3(K2, K, K);
        float M1[9], M2[9]; mm3(M1, Ro, K); mm3(M2, Ro, K2);
#pragma unroll
        for (int i = 0; i < 9; i++) { C[i] = Ro[i]; C[9+i] = M1[i]; C[18+i] = M2[i]; }
        C[27] = rev_p_off[j*3+0]; C[28] = rev_p_off[j*3+1]; C[29] = rev_p_off[j*3+2];

        float Rp[9];
        rpy2r_fast(pri_rpy_off[j*3+0], pri_rpy_off[j*3+1], pri_rpy_off[j*3+2], Rp);
#pragma unroll
        for (int i = 0; i < 9; i++) C[30+i] = Rp[i];
        float pax = pri_axis[j*3+0], pay = pri_axis[j*3+1], paz = pri_axis[j*3+2];
#pragma unroll
        for (int r = 0; r < 3; r++)
            C[39+r] = Rp[r*3+0]*pax + Rp[r*3+1]*pay + Rp[r*3+2]*paz;
        C[42] = pri_p_off[j*3+0]; C[43] = pri_p_off[j*3+1]; C[44] = pri_p_off[j*3+2];

        float Rt[9];
        rpy2r_fast(rpy_track[j*3+0], rpy_track[j*3+1], rpy_track[j*3+2], Rt);
#pragma unroll
        for (int i = 0; i < 9; i++) C[45+i] = Rt[i];
        C[54] = p_track[j*3+0]; C[55] = p_track[j*3+1]; C[56] = p_track[j*3+2];
    }
    __syncthreads();

    // ---- phase 1: local segment product ----
    float R[9] = {1.f,0.f,0.f, 0.f,1.f,0.f, 0.f,0.f,1.f};
    float p[3] = {0.f, 0.f, 0.f};
#pragma unroll
    for (int i = 0; i < 6; i++) {
        if (i < len) {
            const float* C = sC + (jb + i) * CONST_PER_J;
            float R1[9], p1[3];
            joint_apply_c(C, sn[i], ic[i], qp[i], R, p, R1, p1);
        }
    }

    // ---- phase 2: exclusive prefix within 4-lane group via shfl ----
    float P[9] = {1.f,0.f,0.f, 0.f,1.f,0.f, 0.f,0.f,1.f};
    float pp[3] = {0.f, 0.f, 0.f};
    int base = lane & ~3;
#pragma unroll
    for (int k = 0; k < 3; k++) {
        float Lr[9], Lp[3];
#pragma unroll
        for (int t = 0; t < 9; t++) Lr[t] = __shfl_sync(0xffffffffu, R[t], base + k);
#pragma unroll
        for (int t = 0; t < 3; t++) Lp[t] = __shfl_sync(0xffffffffu, p[t], base + k);
        if (k < s) {
            float pn[3];
#pragma unroll
            for (int r = 0; r < 3; r++)
                pn[r] = fmaf(P[r*3+0], Lp[0],
                        fmaf(P[r*3+1], Lp[1],
                        fmaf(P[r*3+2], Lp[2], pp[r])));
            float Rn[9];
            mm3(Rn, P, Lr);
#pragma unroll
            for (int t = 0; t < 9; t++) P[t] = Rn[t];
            pp[0] = pn[0]; pp[1] = pn[1]; pp[2] = pn[2];
        }
    }

    // ---- phase 3: re-run from prefix, pair-drains ----
    float* wbase = sStage + w * WSTRIDE;
    float* regR0 = wbase;
    float* regR1 = wbase + REGSZ;      // also track staging on even i
    float* regP0 = wbase + 2 * REGSZ;
    float* regP1 = wbase + 3 * REGSZ;

    float* outTrk = out;
    float* outRev = out + (size_t)B * 160;
    float* outPri = out + (size_t)B * 480;

#pragma unroll
    for (int t = 0; t < 9; t++) R[t] = P[t];
    p[0] = pp[0]; p[1] = pp[1]; p[2] = pp[2];

    const float4 hom = make_float4(0.f, 0.f, 0.f, 1.f);
    // per-lane invariants
    int l8  = lane >> 3;       // 0..3 (pair-drain record offset)
    int stq = (lane >> 2) & 1; // which slot of the pair
    int mq  = lane & 3;        // quad within matrix
    int l4  = lane >> 2;       // 0..7 (track drain record offset)

#pragma unroll
    for (int i = 0; i < 6; i++) {
        int half = (i & 1);
        if (i < len) {
            const float* C = sC + (jb + i) * CONST_PER_J;
            float R1[9], p1[3];
            joint_apply_c(C, sn[i], ic[i], qp[i], R, p, R1, p1);
            stage12((half ? regR1 : regR0) + lane * 12, R1, p1);
            stage12((half ? regP1 : regP0) + lane * 12, R, p);
            if (!half) {
                // tracking frame (j = jb+i even)
                float Rt[9], pt[3];
                mm3(Rt, R, C + 45);
#pragma unroll
                for (int r = 0; r < 3; r++)
                    pt[r] = fmaf(R[r*3+0], C[54],
                            fmaf(R[r*3+1], C[55],
                            fmaf(R[r*3+2], C[56], p[r])));
                // overwrite R1 region temporarily (free on even i)
                stage12(regR1 + lane * 12, Rt, pt);
            }
        }
        __syncwarp();

        if (!half) {
            // ---- track drain (scattered 64B; 1/5 of traffic) ----
            if (i < 4) {
#pragma unroll
                for (int k = 0; k < 4; k++) {
                    int r = k * 8 + l4;            // record 0..31
                    int bbd = r >> 2, sd = r & 3;
                    int slot = ((5 * sd + (sd & 1)) >> 1) + (i >> 1);
                    int gbd = wb0 + bbd; if (gbd >= B) gbd = B - 1;
                    float4 v = (mq < 3) ? *(const float4*)(regR1 + r * 12 + mq * 4) : hom;
                    *(float4*)(outTrk + ((size_t)gbd * 10 + slot) * 16 + mq * 4) = v;
                }
            } else {
#pragma unroll
                for (int k = 0; k < 2; k++) {
                    int r = k * 8 + l4;            // 0..15
                    int bbd = r >> 1, sd = (r & 1) * 2;
                    int slot = ((5 * sd) >> 1) + 2;   // 2 or 7
                    int src = bbd * 4 + sd;
                    int gbd = wb0 + bbd; if (gbd >= B) gbd = B - 1;
                    float4 v = (mq < 3) ? *(const float4*)(regR1 + src * 12 + mq * 4) : hom;
                    *(float4*)(outTrk + ((size_t)gbd * 10 + slot) * 16 + mq * 4) = v;
                }
            }
        } else {
            // ---- rev/pri pair drains: 128B-contiguous record pairs ----
            if (i < 5) {
#pragma unroll
                for (int k = 0; k < 8; k++) {
                    int r = k * 4 + l8;            // record 0..31
                    int bbd = r >> 2, sd = r & 3;
                    int slot = 5 * sd + (sd & 1) + (i - 1) + stq;
                    int gbd = wb0 + bbd; if (gbd >= B) gbd = B - 1;
                    size_t d = ((size_t)gbd * J + slot) * 16 + mq * 4;
                    float4 vr = (mq < 3) ? *(const float4*)((stq ? regR1 : regR0) + r * 12 + mq * 4) : hom;
                    float4 vp = (mq < 3) ? *(const float4*)((stq ? regP1 : regP0) + r * 12 + mq * 4) : hom;
                    *(float4*)(outRev + d) = vr;
                    *(float4*)(outPri + d) = vp;
                }
            } else {
#pragma unroll
                for (int k = 0; k < 4; k++) {
                    int r = k * 4 + l8;            // 0..15
                    int bbd = r >> 1, sd = (r & 1) * 2;
                    int src = bbd * 4 + sd;
                    int slot = 5 * sd + 4 + stq;
                    int gbd = wb0 + bbd; if (gbd >= B) gbd = B - 1;
                    size_t d = ((size_t)gbd * J + slot) * 16 + mq * 4;
                    float4 vr = (mq < 3) ? *(const float4*)((stq ? regR1 : regR0) + src * 12 + mq * 4) : hom;
                    float4 vp = (mq < 3) ? *(const float4*)((stq ? regP1 : regP0) + src * 12 + mq * 4) : hom;
                    *(float4*)(outRev + d) = vr;
                    *(float4*)(outPri + d) = vp;
                }
            }
        }
        __syncwarp();
    }
}

extern "C" void kernel_launch(void* const* d_in, const int* in_sizes, int n_in,
                              void* d_out, int out_size) {
    const float* rev_q       = (const float*)d_in[0];
    const float* pri_q       = (const float*)d_in[1];
    const float* rev_p_off   = (const float*)d_in[2];
    const float* rev_rpy_off = (const float*)d_in[3];
    const float* pri_p_off   = (const float*)d_in[4];
    const float* pri_rpy_off = (const float*)d_in[5];
    const float* rev_axis    = (const float*)d_in[6];
    const float* pri_axis    = (const float*)d_in[7];
    const float* p_track     = (const float*)d_in[8];
    const float* rpy_track   = (const float*)d_in[9];
    float* out = (float*)d_out;

    int B = in_sizes[0] / J;
    int grid = (B + 31) / 32;
    fk_kernel<<<grid, 128>>>(rev_q, pri_q,
                             rev_p_off, rev_rpy_off, pri_p_off, pri_rpy_off,
                             rev_axis, pri_axis, p_track, rpy_track, out, B);
}

// round 11
// speedup vs baseline: 1.4072x; 1.0703x over previous
#include <cuda_runtime.h>
#include <math.h>

#define J 20
#define CONST_PER_J 57
// per joint: M0[9]@0, M1[9]@9, M2[9]@18, p_rev[3]@27,
//            Rpri[9]@30, v_pri[3]@39, p_pri[3]@42, Rtrk[9]@45, p_trk[3]@54

__device__ __forceinline__ int seg_base(int sd) { return (5 * sd + (sd & 1)) >> 1; }

__device__ __forceinline__ void rpy2r_fast(float r, float p, float y, float* R) {
    float cr, sr, cp, sp, cy, sy;
    __sincosf(r, &sr, &cr);
    __sincosf(p, &sp, &cp);
    __sincosf(y, &sy, &cy);
    R[0] = cy * cp; R[1] = cy * sp * sr - sy * cr; R[2] = cy * sp * cr + sy * sr;
    R[3] = sy * cp; R[4] = sy * sp * sr + cy * cr; R[5] = sy * sp * cr - cy * sr;
    R[6] = -sp;     R[7] = cp * sr;                R[8] = cp * cr;
}

__device__ __forceinline__ void mm3(float* D, const float* A, const float* B) {
#pragma unroll
    for (int r = 0; r < 3; r++)
#pragma unroll
        for (int c = 0; c < 3; c++)
            D[r * 3 + c] = fmaf(A[r * 3 + 0], B[0 * 3 + c],
                           fmaf(A[r * 3 + 1], B[1 * 3 + c],
                                A[r * 3 + 2] * B[2 * 3 + c]));
}

__device__ __forceinline__ void joint_apply_c(const float* C, float s, float ic, float qp,
                                              float R[9], float p[3],
                                              float R1[9], float p1[3]) {
    float Rs[9];
#pragma unroll
    for (int i = 0; i < 9; i++)
        Rs[i] = fmaf(s, C[9 + i], fmaf(ic, C[18 + i], C[i]));
    mm3(R1, R, Rs);
#pragma unroll
    for (int r = 0; r < 3; r++)
        p1[r] = fmaf(R[r * 3 + 0], C[27],
                fmaf(R[r * 3 + 1], C[28],
                fmaf(R[r * 3 + 2], C[29], p[r])));
    float ps0 = fmaf(qp, C[39], C[42]);
    float ps1 = fmaf(qp, C[40], C[43]);
    float ps2 = fmaf(qp, C[41], C[44]);
    float R2[9];
    mm3(R2, R1, C + 30);
#pragma unroll
    for (int r = 0; r < 3; r++)
        p[r] = fmaf(R1[r * 3 + 0], ps0,
               fmaf(R1[r * 3 + 1], ps1,
               fmaf(R1[r * 3 + 2], ps2, p1[r])));
#pragma unroll
    for (int i = 0; i < 9; i++) R[i] = R2[i];
}

__device__ __forceinline__ void stage12(float* dst, const float R[9], const float p[3]) {
    float4* sp = (float4*)dst;
    sp[0] = make_float4(R[0], R[1], R[2], p[0]);
    sp[1] = make_float4(R[3], R[4], R[5], p[1]);
    sp[2] = make_float4(R[6], R[7], R[8], p[2]);
}

__global__ void __launch_bounds__(128, 7)
fk_kernel(const float* __restrict__ rev_q, const float* __restrict__ pri_q,
          const float* __restrict__ rev_p_off, const float* __restrict__ rev_rpy_off,
          const float* __restrict__ pri_p_off, const float* __restrict__ pri_rpy_off,
          const float* __restrict__ rev_axis, const float* __restrict__ pri_axis,
          const float* __restrict__ p_track, const float* __restrict__ rpy_track,
          float* __restrict__ out, int B) {
    __shared__ float sC[J * CONST_PER_J];
    __shared__ float sStage[4][32 * 12];

    int tid  = threadIdx.x;
    int lane = tid & 31;
    int w    = tid >> 5;
    int bb   = lane >> 3;              // batch within warp (0..3)
    int s    = lane & 7;               // segment id (0..7)
    int wb0  = blockIdx.x * 16 + w * 4;
    int gb   = wb0 + bb; if (gb >= B) gb = B - 1;

    int len = 3 - (s & 1);             // 3,2,3,2,...
    int jb  = seg_base(s);             // 0,3,5,8,10,13,15,18

    // q loads + trig early (overlap with const prep)
    float sn[3], ic[3], qp[3];
#pragma unroll
    for (int i = 0; i < 3; i++) {
        sn[i] = 0.f; ic[i] = 0.f; qp[i] = 0.f;
        if (i < len) {
            float q = rev_q[(size_t)gb * J + jb + i];
            float c;
            __sincosf(q, &sn[i], &c);
            ic[i] = 1.f - c;
            qp[i] = pri_q[(size_t)gb * J + jb + i];
        }
    }

    // ---- in-block constant prep (threads 0..19), unchanged from R4 ----
    if (tid < J) {
        int j = tid;
        float* C = sC + j * CONST_PER_J;
        float Ro[9];
        rpy2r_fast(rev_rpy_off[j*3+0], rev_rpy_off[j*3+1], rev_rpy_off[j*3+2], Ro);
        float ax = rev_axis[j*3+0], ay = rev_axis[j*3+1], az = rev_axis[j*3+2];
        float n = sqrtf(ax*ax + ay*ay + az*az) + 1e-12f;
        ax /= n; ay /= n; az /= n;
        float K[9]  = {0.f, -az, ay,  az, 0.f, -ax,  -ay, ax, 0.f};
        float K2[9]; mm3(K2, K, K);
        float M1[9], M2[9]; mm3(M1, Ro, K); mm3(M2, Ro, K2);
#pragma unroll
        for (int i = 0; i < 9; i++) { C[i] = Ro[i]; C[9+i] = M1[i]; C[18+i] = M2[i]; }
        C[27] = rev_p_off[j*3+0]; C[28] = rev_p_off[j*3+1]; C[29] = rev_p_off[j*3+2];

        float Rp[9];
        rpy2r_fast(pri_rpy_off[j*3+0], pri_rpy_off[j*3+1], pri_rpy_off[j*3+2], Rp);
#pragma unroll
        for (int i = 0; i < 9; i++) C[30+i] = Rp[i];
        float pax = pri_axis[j*3+0], pay = pri_axis[j*3+1], paz = pri_axis[j*3+2];
#pragma unroll
        for (int r = 0; r < 3; r++)
            C[39+r] = Rp[r*3+0]*pax + Rp[r*3+1]*pay + Rp[r*3+2]*paz;
        C[42] = pri_p_off[j*3+0]; C[43] = pri_p_off[j*3+1]; C[44] = pri_p_off[j*3+2];

        float Rt[9];
        rpy2r_fast(rpy_track[j*3+0], rpy_track[j*3+1], rpy_track[j*3+2], Rt);
#pragma unroll
        for (int i = 0; i < 9; i++) C[45+i] = Rt[i];
        C[54] = p_track[j*3+0]; C[55] = p_track[j*3+1]; C[56] = p_track[j*3+2];
    }
    __syncthreads();

    // ---- phase 1: local segment product (<=3 applies) ----
    float R[9] = {1.f,0.f,0.f, 0.f,1.f,0.f, 0.f,0.f,1.f};
    float p[3] = {0.f, 0.f, 0.f};
#pragma unroll
    for (int i = 0; i < 3; i++) {
        if (i < len) {
            const float* C = sC + (jb + i) * CONST_PER_J;
            float R1[9], p1[3];
            joint_apply_c(C, sn[i], ic[i], qp[i], R, p, R1, p1);
        }
    }

    // ---- phase 2: exclusive prefix within 8-lane group via shfl ----
    float P[9] = {1.f,0.f,0.f, 0.f,1.f,0.f, 0.f,0.f,1.f};
    float pp[3] = {0.f, 0.f, 0.f};
    int base8 = lane & ~7;
#pragma unroll
    for (int k = 0; k < 7; k++) {
        float Lr[9], Lp[3];
#pragma unroll
        for (int t = 0; t < 9; t++) Lr[t] = __shfl_sync(0xffffffffu, R[t], base8 + k);
#pragma unroll
        for (int t = 0; t < 3; t++) Lp[t] = __shfl_sync(0xffffffffu, p[t], base8 + k);
        if (k < s) {
            float pn[3];
#pragma unroll
            for (int r = 0; r < 3; r++)
                pn[r] = fmaf(P[r*3+0], Lp[0],
                        fmaf(P[r*3+1], Lp[1],
                        fmaf(P[r*3+2], Lp[2], pp[r])));
            float Rn[9];
            mm3(Rn, P, Lr);
#pragma unroll
            for (int t = 0; t < 9; t++) P[t] = Rn[t];
            pp[0] = pn[0]; pp[1] = pn[1]; pp[2] = pn[2];
        }
    }

    // ---- phase 3: re-run from prefix, R4-style staged emits ----
    float* stg = sStage[w];
    float* outTrk = out;
    float* outRev = out + (size_t)B * 160;
    float* outPri = out + (size_t)B * 480;

#pragma unroll
    for (int t = 0; t < 9; t++) R[t] = P[t];
    p[0] = pp[0]; p[1] = pp[1]; p[2] = pp[2];

    const float4 hom = make_float4(0.f, 0.f, 0.f, 1.f);

#pragma unroll
    for (int i = 0; i < 3; i++) {
        bool active = (i < len);
        float R1[9], p1[3];
        if (active) {
            const float* C = sC + (jb + i) * CONST_PER_J;
            joint_apply_c(C, sn[i], ic[i], qp[i], R, p, R1, p1);
        }

        // ---- rev emit ----
        if (active) stage12(stg + lane * 12, R1, p1);
        __syncwarp();
        if (i < 2) {
#pragma unroll
            for (int k = 0; k < 4; k++) {
                int c = k * 32 + lane, idx = c >> 2, m = c & 3;
                int bbd = idx >> 3, sd = idx & 7;
                int gbd = wb0 + bbd; if (gbd >= B) gbd = B - 1;
                int slot = seg_base(sd) + i;
                float4 v = (m < 3) ? *(const float4*)(stg + idx * 12 + 4 * m) : hom;
                *(float4*)(outRev + ((size_t)gbd * J + slot) * 16 + 4 * m) = v;
            }
        } else {
#pragma unroll
            for (int k = 0; k < 2; k++) {
                int c = k * 32 + lane, idx16 = c >> 2, m = c & 3;
                int bbd = idx16 >> 2, sd = (idx16 & 3) * 2;
                int src = bbd * 8 + sd;
                int gbd = wb0 + bbd; if (gbd >= B) gbd = B - 1;
                int slot = seg_base(sd) + 2;
                float4 v = (m < 3) ? *(const float4*)(stg + src * 12 + 4 * m) : hom;
                *(float4*)(outRev + ((size_t)gbd * J + slot) * 16 + 4 * m) = v;
            }
        }
        __syncwarp();

        // ---- pri emit ----
        if (active) stage12(stg + lane * 12, R, p);
        __syncwarp();
        if (i < 2) {
#pragma unroll
            for (int k = 0; k < 4; k++) {
                int c = k * 32 + lane, idx = c >> 2, m = c & 3;
                int bbd = idx >> 3, sd = idx & 7;
                int gbd = wb0 + bbd; if (gbd >= B) gbd = B - 1;
                int slot = seg_base(sd) + i;
                float4 v = (m < 3) ? *(const float4*)(stg + idx * 12 + 4 * m) : hom;
                *(float4*)(outPri + ((size_t)gbd * J + slot) * 16 + 4 * m) = v;
            }
        } else {
#pragma unroll
            for (int k = 0; k < 2; k++) {
                int c = k * 32 + lane, idx16 = c >> 2, m = c & 3;
                int bbd = idx16 >> 2, sd = (idx16 & 3) * 2;
                int src = bbd * 8 + sd;
                int gbd = wb0 + bbd; if (gbd >= B) gbd = B - 1;
                int slot = seg_base(sd) + 2;
                float4 v = (m < 3) ? *(const float4*)(stg + src * 12 + 4 * m) : hom;
                *(float4*)(outPri + ((size_t)gbd * J + slot) * 16 + 4 * m) = v;
            }
        }
        __syncwarp();

        // ---- track emit (joint jb+i even) ----
        bool owner = active && (((jb + i) & 1) == 0);
        if (owner) {
            const float* C = sC + (jb + i) * CONST_PER_J;
            float Rt[9], pt[3];
            mm3(Rt, R, C + 45);
#pragma unroll
            for (int r = 0; r < 3; r++)
                pt[r] = fmaf(R[r*3+0], C[54],
                        fmaf(R[r*3+1], C[55],
                        fmaf(R[r*3+2], C[56], p[r])));
            stage12(stg + lane * 12, Rt, pt);
        }
        __syncwarp();
        if (i < 2) {
            // owners: i=0 -> sd = 2t+(t&1) in {0,3,4,7}; i=1 -> sd = 2t+1-(t&1) in {1,2,5,6}
#pragma unroll
            for (int k = 0; k < 2; k++) {
                int c = k * 32 + lane, rec = c >> 2, m = c & 3;   // rec 0..15
                int bbd = rec >> 2, t = rec & 3;
                int sd = (i == 0) ? (2 * t + (t & 1)) : (2 * t + 1 - (t & 1));
                int src = bbd * 8 + sd;
                int gbd = wb0 + bbd; if (gbd >= B) gbd = B - 1;
                int slot = (seg_base(sd) + i) >> 1;
                float4 v = (m < 3) ? *(const float4*)(stg + src * 12 + 4 * m) : hom;
                *(float4*)(outTrk + ((size_t)gbd * 10 + slot) * 16 + 4 * m) = v;
            }
        } else {
            // owners: sd in {0,4} -> slots {1,6}; 8 records
            {
                int rec = lane >> 2, m = lane & 3;    // rec 0..7
                int bbd = rec >> 1, t = rec & 1;
                int sd = 4 * t;
                int src = bbd * 8 + sd;
                int gbd = wb0 + bbd; if (gbd >= B) gbd = B - 1;
                int slot = (seg_base(sd) + 2) >> 1;
                float4 v = (m < 3) ? *(const float4*)(stg + src * 12 + 4 * m) : hom;
                *(float4*)(outTrk + ((size_t)gbd * 10 + slot) * 16 + 4 * m) = v;
            }
        }
        __syncwarp();
    }
}

extern "C" void kernel_launch(void* const* d_in, const int* in_sizes, int n_in,
                              void* d_out, int out_size) {
    const float* rev_q       = (const float*)d_in[0];
    const float* pri_q       = (const float*)d_in[1];
    const float* rev_p_off   = (const float*)d_in[2];
    const float* rev_rpy_off = (const float*)d_in[3];
    const float* pri_p_off   = (const float*)d_in[4];
    const float* pri_rpy_off = (const float*)d_in[5];
    const float* rev_axis    = (const float*)d_in[6];
    const float* pri_axis    = (const float*)d_in[7];
    const float* p_track     = (const float*)d_in[8];
    const float* rpy_track   = (const float*)d_in[9];
    float* out = (float*)d_out;

    int B = in_sizes[0] / J;
    int grid = (B + 15) / 16;
    fk_kernel<<<grid, 128>>>(rev_q, pri_q,
                             rev_p_off, rev_rpy_off, pri_p_off, pri_rpy_off,
                             rev_axis, pri_axis, p_track, rpy_track, out, B);
}

// round 12
// speedup vs baseline: 1.5136x; 1.0756x over previous
#include <cuda_runtime.h>
#include <math.h>

#define J 20
#define JPS 5
#define CONST_PER_J 57
#define REGSZ 384
// per joint: M0[9]@0, M1[9]@9, M2[9]@18, p_rev[3]@27,
//            Rpri[9]@30, v_pri[3]@39, p_pri[3]@42, Rtrk[9]@45, p_trk[3]@54

__device__ __forceinline__ void rpy2r_fast(float r, float p, float y, float* R) {
    float cr, sr, cp, sp, cy, sy;
    __sincosf(r, &sr, &cr);
    __sincosf(p, &sp, &cp);
    __sincosf(y, &sy, &cy);
    R[0] = cy * cp; R[1] = cy * sp * sr - sy * cr; R[2] = cy * sp * cr + sy * sr;
    R[3] = sy * cp; R[4] = sy * sp * sr + cy * cr; R[5] = sy * sp * cr - cy * sr;
    R[6] = -sp;     R[7] = cp * sr;                R[8] = cp * cr;
}

__device__ __forceinline__ void mm3(float* D, const float* A, const float* B) {
#pragma unroll
    for (int r = 0; r < 3; r++)
#pragma unroll
        for (int c = 0; c < 3; c++)
            D[r * 3 + c] = fmaf(A[r * 3 + 0], B[0 * 3 + c],
                           fmaf(A[r * 3 + 1], B[1 * 3 + c],
                                A[r * 3 + 2] * B[2 * 3 + c]));
}

__device__ __forceinline__ void joint_apply_c(const float* C, float s, float ic, float qp,
                                              float R[9], float p[3],
                                              float R1[9], float p1[3]) {
    float Rs[9];
#pragma unroll
    for (int i = 0; i < 9; i++)
        Rs[i] = fmaf(s, C[9 + i], fmaf(ic, C[18 + i], C[i]));
    mm3(R1, R, Rs);
#pragma unroll
    for (int r = 0; r < 3; r++)
        p1[r] = fmaf(R[r * 3 + 0], C[27],
                fmaf(R[r * 3 + 1], C[28],
                fmaf(R[r * 3 + 2], C[29], p[r])));
    float ps0 = fmaf(qp, C[39], C[42]);
    float ps1 = fmaf(qp, C[40], C[43]);
    float ps2 = fmaf(qp, C[41], C[44]);
    float R2[9];
    mm3(R2, R1, C + 30);
#pragma unroll
    for (int r = 0; r < 3; r++)
        p[r] = fmaf(R1[r * 3 + 0], ps0,
               fmaf(R1[r * 3 + 1], ps1,
               fmaf(R1[r * 3 + 2], ps2, p1[r])));
#pragma unroll
    for (int i = 0; i < 9; i++) R[i] = R2[i];
}

__device__ __forceinline__ void stage12(float* dst, const float R[9], const float p[3]) {
    float4* sp = (float4*)dst;
    sp[0] = make_float4(R[0], R[1], R[2], p[0]);
    sp[1] = make_float4(R[3], R[4], R[5], p[1]);
    sp[2] = make_float4(R[6], R[7], R[8], p[2]);
}

__global__ void __launch_bounds__(128, 7)
fk_kernel(const float* __restrict__ rev_q, const float* __restrict__ pri_q,
          const float* __restrict__ rev_p_off, const float* __restrict__ rev_rpy_off,
          const float* __restrict__ pri_p_off, const float* __restrict__ pri_rpy_off,
          const float* __restrict__ rev_axis, const float* __restrict__ pri_axis,
          const float* __restrict__ p_track, const float* __restrict__ rpy_track,
          float* __restrict__ out, int B) {
    __shared__ float sC[J * CONST_PER_J];
    __shared__ float sStage[4][3 * REGSZ];   // per warp: rev, pri, trk regions

    int tid  = threadIdx.x;
    int lane = tid & 31;
    int w    = tid >> 5;
    int bb   = lane >> 2;
    int s    = lane & 3;
    int wb0  = blockIdx.x * 32 + w * 8;
    int gb   = wb0 + bb; if (gb >= B) gb = B - 1;

    // q loads + trig early (overlap with const prep)
    float sn[JPS], ic[JPS], qp[JPS];
#pragma unroll
    for (int i = 0; i < JPS; i++) {
        float q = rev_q[(size_t)gb * J + s * JPS + i];
        float c;
        __sincosf(q, &sn[i], &c);
        ic[i] = 1.f - c;
        qp[i] = pri_q[(size_t)gb * J + s * JPS + i];
    }

    // ---- in-block constant prep (threads 0..19), R4-identical ----
    if (tid < J) {
        int j = tid;
        float* C = sC + j * CONST_PER_J;
        float Ro[9];
        rpy2r_fast(rev_rpy_off[j*3+0], rev_rpy_off[j*3+1], rev_rpy_off[j*3+2], Ro);
        float ax = rev_axis[j*3+0], ay = rev_axis[j*3+1], az = rev_axis[j*3+2];
        float n = sqrtf(ax*ax + ay*ay + az*az) + 1e-12f;
        ax /= n; ay /= n; az /= n;
        float K[9]  = {0.f, -az, ay,  az, 0.f, -ax,  -ay, ax, 0.f};
        float K2[9]; mm3(K2, K, K);
        float M1[9], M2[9]; mm3(M1, Ro, K); mm3(M2, Ro, K2);
#pragma unroll
        for (int i = 0; i < 9; i++) { C[i] = Ro[i]; C[9+i] = M1[i]; C[18+i] = M2[i]; }
        C[27] = rev_p_off[j*3+0]; C[28] = rev_p_off[j*3+1]; C[29] = rev_p_off[j*3+2];

        float Rp[9];
        rpy2r_fast(pri_rpy_off[j*3+0], pri_rpy_off[j*3+1], pri_rpy_off[j*3+2], Rp);
#pragma unroll
        for (int i = 0; i < 9; i++) C[30+i] = Rp[i];
        float pax = pri_axis[j*3+0], pay = pri_axis[j*3+1], paz = pri_axis[j*3+2];
#pragma unroll
        for (int r = 0; r < 3; r++)
            C[39+r] = Rp[r*3+0]*pax + Rp[r*3+1]*pay + Rp[r*3+2]*paz;
        C[42] = pri_p_off[j*3+0]; C[43] = pri_p_off[j*3+1]; C[44] = pri_p_off[j*3+2];

        float Rt[9];
        rpy2r_fast(rpy_track[j*3+0], rpy_track[j*3+1], rpy_track[j*3+2], Rt);
#pragma unroll
        for (int i = 0; i < 9; i++) C[45+i] = Rt[i];
        C[54] = p_track[j*3+0]; C[55] = p_track[j*3+1]; C[56] = p_track[j*3+2];
    }
    __syncthreads();

    // ---- phase 1: local segment product ----
    float R[9] = {1.f,0.f,0.f, 0.f,1.f,0.f, 0.f,0.f,1.f};
    float p[3] = {0.f, 0.f, 0.f};
#pragma unroll
    for (int i = 0; i < JPS; i++) {
        const float* C = sC + (s * JPS + i) * CONST_PER_J;
        float R1[9], p1[3];
        joint_apply_c(C, sn[i], ic[i], qp[i], R, p, R1, p1);
    }

    // ---- phase 2: exclusive prefix within 4-lane group via shfl ----
    float P[9] = {1.f,0.f,0.f, 0.f,1.f,0.f, 0.f,0.f,1.f};
    float pp[3] = {0.f, 0.f, 0.f};
    int base = lane & ~3;
#pragma unroll
    for (int k = 0; k < 3; k++) {
        float Lr[9], Lp[3];
#pragma unroll
        for (int t = 0; t < 9; t++) Lr[t] = __shfl_sync(0xffffffffu, R[t], base + k);
#pragma unroll
        for (int t = 0; t < 3; t++) Lp[t] = __shfl_sync(0xffffffffu, p[t], base + k);
        if (k < s) {
            float pn[3];
#pragma unroll
            for (int r = 0; r < 3; r++)
                pn[r] = fmaf(P[r*3+0], Lp[0],
                        fmaf(P[r*3+1], Lp[1],
                        fmaf(P[r*3+2], Lp[2], pp[r])));
            float Rn[9];
            mm3(Rn, P, Lr);
#pragma unroll
            for (int t = 0; t < 9; t++) P[t] = Rn[t];
            pp[0] = pn[0]; pp[1] = pn[1]; pp[2] = pn[2];
        }
    }

    // ---- phase 3: re-run from prefix, merged single-sync emits ----
    float* regA = sStage[w];               // rev
    float* regB = sStage[w] + REGSZ;       // pri
    float* regC = sStage[w] + 2 * REGSZ;   // trk
    float* outTrk = out;
    float* outRev = out + (size_t)B * 160;
    float* outPri = out + (size_t)B * 480;

#pragma unroll
    for (int t = 0; t < 9; t++) R[t] = P[t];
    p[0] = pp[0]; p[1] = pp[1]; p[2] = pp[2];

    const float4 hom = make_float4(0.f, 0.f, 0.f, 1.f);

#pragma unroll
    for (int i = 0; i < JPS; i++) {
        int j = s * JPS + i;
        const float* C = sC + j * CONST_PER_J;
        float R1[9], p1[3];
        joint_apply_c(C, sn[i], ic[i], qp[i], R, p, R1, p1);

        // stage all three frames, then one sync
        stage12(regA + lane * 12, R1, p1);
        stage12(regB + lane * 12, R, p);
        bool owner = (((s ^ i) & 1) == 0);   // j = 5s+i even
        if (owner) {
            float Rt[9], pt[3];
            mm3(Rt, R, C + 45);
#pragma unroll
            for (int r = 0; r < 3; r++)
                pt[r] = fmaf(R[r*3+0], C[54],
                        fmaf(R[r*3+1], C[55],
                        fmaf(R[r*3+2], C[56], p[r])));
            stage12(regC + lane * 12, Rt, pt);
        }
        __syncwarp();

        // drain rev + pri (R4 index math), fully back-to-back for ILP
#pragma unroll
        for (int k = 0; k < 4; k++) {
            int c = k * 32 + lane, idx = c >> 2, m = c & 3;
            int bbd = idx >> 2, s2 = idx & 3;
            int gbd = wb0 + bbd; if (gbd >= B) gbd = B - 1;
            size_t d = ((size_t)gbd * J + 5 * s2 + i) * 16 + 4 * m;
            float4 vr = (m < 3) ? *(const float4*)(regA + idx * 12 + 4 * m) : hom;
            float4 vp = (m < 3) ? *(const float4*)(regB + idx * 12 + 4 * m) : hom;
            *(float4*)(outRev + d) = vr;
            *(float4*)(outPri + d) = vp;
        }
        // drain track (R4 emit_track mapping)
#pragma unroll
        for (int k = 0; k < 2; k++) {
            int c = k * 32 + lane, idx16 = c >> 2, m = c & 3;
            int bbd = idx16 >> 1, pos = idx16 & 1;
            int s2 = (i & 1) + 2 * pos;
            int src = bbd * 4 + s2;
            int slot = (5 * s2 + i) >> 1;
            int gbd = wb0 + bbd; if (gbd >= B) gbd = B - 1;
            float4 v = (m < 3) ? *(const float4*)(regC + src * 12 + 4 * m) : hom;
            *(float4*)(outTrk + ((size_t)gbd * 10 + slot) * 16 + 4 * m) = v;
        }
        __syncwarp();
    }
}

extern "C" void kernel_launch(void* const* d_in, const int* in_sizes, int n_in,
                              void* d_out, int out_size) {
    const float* rev_q       = (const float*)d_in[0];
    const float* pri_q       = (const float*)d_in[1];
    const float* rev_p_off   = (const float*)d_in[2];
    const float* rev_rpy_off = (const float*)d_in[3];
    const float* pri_p_off   = (const float*)d_in[4];
    const float* pri_rpy_off = (const float*)d_in[5];
    const float* rev_axis    = (const float*)d_in[6];
    const float* pri_axis    = (const float*)d_in[7];
    const float* p_track     = (const float*)d_in[8];
    const float* rpy_track   = (const float*)d_in[9];
    float* out = (float*)d_out;

    int B = in_sizes[0] / J;
    int grid = (B + 31) / 32;
    fk_kernel<<<grid, 128>>>(rev_q, pri_q,
                             rev_p_off, rev_rpy_off, pri_p_off, pri_rpy_off,
                             rev_axis, pri_axis, p_track, rpy_track, out, B);
}